// round 11
// baseline (speedup 1.0000x reference)
#include <cuda_runtime.h>
#include <math.h>

#define NUM_ITEMS  10000
#define NUM_USERS  10000
#define NUM_GROUPS 5000
#define EMB_DIM    64
#define BATCH      16384
#define NCOLS      10000
#define PANEL      500                 // columns per panel (2000 B segment, 16B-aligned)
#define NPANELS    20                  // 10000 / 500
#define ROWGRP     15                  // row groups -> 20*15 = 300 CTAs
#define NF4        125                 // float4 per row segment
#define SMEM_BYTES (PANEL * 32 * sizeof(float2))   // 128000 B

// Scratch (allocation-free rule: __device__ globals)
__device__ float g_user_sums[NUM_USERS * EMB_DIM];   // raw sums (divided at k2 stage)
__device__ int   g_ucnt[NUM_USERS];
__device__ float g_group_sums[NUM_GROUPS * EMB_DIM]; // raw sums (divided in MLP)
__device__ int   g_gcnt[NUM_GROUPS];

// ---------------------------------------------------------------------------
__global__ void zero_kernel() {
    const int i = blockIdx.x * blockDim.x + threadIdx.x;
    if (i < NUM_USERS * EMB_DIM)  g_user_sums[i]  = 0.f;
    if (i < NUM_GROUPS * EMB_DIM) g_group_sums[i] = 0.f;
    if (i < NUM_USERS)            g_ucnt[i] = 0;
    if (i < NUM_GROUPS)           g_gcnt[i] = 0;
}

// ---------------------------------------------------------------------------
// Panel aggregation. blockIdx.x = panel, blockIdx.y = row group.
// Stage: table rows [panel*500, panel*500+500) -> smem as [500][32] float2
//        (DIV_STAGE: divide each row by clamp(tcnt,1) while staging).
// Stream: each warp scans 2 rows/iter x 4 LDG.128 per row (MLP=8, __ldcs),
//         byte-pack detection (entries are exactly {0.0f,1.0f}: byte3==0x3F),
//         hits gathered from SMEM (conflict-free broadcast), partial sums and
//         counts RED-accumulated to global.
// ---------------------------------------------------------------------------
template <bool DIV_STAGE>
__global__ __launch_bounds__(512)
void panel_aggregate(const float* __restrict__ mat,
                     const float* __restrict__ table,
                     const int*   __restrict__ tcnt,
                     float* __restrict__ out_sums,
                     int*   __restrict__ out_cnt,
                     int nrows)
{
    extern __shared__ float2 s_emb[];             // [PANEL][32]
    const int tid  = threadIdx.x;
    const int lane = tid & 31;
    const int wid  = tid >> 5;                    // 16 warps
    const int panel_base = blockIdx.x * PANEL;

    // ---- stage the table panel ----
    const float2* __restrict__ t2 = (const float2*)table;
    for (int i = tid; i < PANEL * 32; i += 512) {
        const int local = i >> 5;
        float2 v = t2[(size_t)(panel_base + local) * 32 + (i & 31)];
        if (DIV_STAGE) {
            const float inv = 1.f / fmaxf((float)tcnt[panel_base + local], 1.f);
            v.x *= inv; v.y *= inv;
        }
        s_emb[i] = v;
    }
    __syncthreads();

    const int rpg    = (nrows + gridDim.y - 1) / gridDim.y;
    const int rstart = blockIdx.y * rpg;
    const int rend   = min(rstart + rpg, nrows);

    for (int r0 = rstart + wid * 2; r0 < rend; r0 += 32) {
        const int nrow2 = (r0 + 1 < rend) ? 2 : 1;

        // ---- prefetch both rows' segments (up to 8 independent LDG.128) ----
        float4 a[2][4];
        #pragma unroll
        for (int rr = 0; rr < 2; ++rr) {
            if (rr < nrow2) {
                const float4* __restrict__ rp =
                    (const float4*)(mat + (size_t)(r0 + rr) * NCOLS + panel_base);
                #pragma unroll
                for (int u = 0; u < 4; ++u) {
                    const int c = lane + 32 * u;
                    a[rr][u] = (c < NF4) ? __ldcs(&rp[c])
                                         : make_float4(0.f, 0.f, 0.f, 0.f);
                }
            }
        }

        // ---- per row: detect, gather from smem, RED out ----
        #pragma unroll
        for (int rr = 0; rr < 2; ++rr) {
            if (rr >= nrow2) break;

            unsigned m = 0;                       // bit 8e+u: chunk u, element e
            #pragma unroll
            for (int u = 0; u < 4; ++u) {
                const unsigned p =
                    __byte_perm(__float_as_uint(a[rr][u].x),
                                __float_as_uint(a[rr][u].y), 0x0073) |
                    __byte_perm(__float_as_uint(a[rr][u].z),
                                __float_as_uint(a[rr][u].w), 0x7300);
                m |= (p & 0x01010101u) << u;
            }
            const int cnt  = __popc(m);
            const int rtot = __reduce_add_sync(0xffffffffu, cnt);
            if (rtot == 0) continue;              // warp-uniform

            float2 acc = make_float2(0.f, 0.f);
            unsigned hm = __ballot_sync(0xffffffffu, m != 0u);
            while (hm) {
                const int l = __ffs(hm) - 1;
                hm &= hm - 1;
                unsigned mm = __shfl_sync(0xffffffffu, m, l);
                while (mm) {
                    const int b = __ffs(mm) - 1;  // b = 8e + u
                    mm &= mm - 1;
                    const int item = 4 * l + 128 * (b & 7) + (b >> 3);
                    const float2 t = s_emb[item * 32 + lane];
                    acc.x += t.x; acc.y += t.y;
                }
            }

            const int row = r0 + rr;
            atomicAdd(&out_sums[(size_t)row * EMB_DIM + 2 * lane],     acc.x);
            atomicAdd(&out_sums[(size_t)row * EMB_DIM + 2 * lane + 1], acc.y);
            if (lane == 0) atomicAdd(&out_cnt[row], rtot);
        }
    }
}

// ---------------------------------------------------------------------------
// MLP: y = sigmoid(relu([gs[g]/gcnt[g], ie[it]] @ W1 + b1) @ W2 + b2)
// (group division folded in; raw-count divisor, no clamp, per reference)
// ---------------------------------------------------------------------------
__global__ void mlp_kernel(const float* __restrict__ group_sums,
                           const int*   __restrict__ gcnt,
                           const float* __restrict__ item_emb,
                           const float* __restrict__ W1,  // [128, 8]
                           const float* __restrict__ b1,  // [8]
                           const float* __restrict__ W2,  // [8, 1]
                           const float* __restrict__ b2,  // [1]
                           const int*   __restrict__ gidx,
                           const int*   __restrict__ iidx,
                           float* __restrict__ out,
                           int batch)
{
    __shared__ float sW1[2 * EMB_DIM * 8];
    __shared__ float sb1[8];
    __shared__ float sW2[8];
    __shared__ float sb2;

    for (int i = threadIdx.x; i < 2 * EMB_DIM * 8; i += blockDim.x)
        sW1[i] = W1[i];
    if (threadIdx.x < 8) {
        sb1[threadIdx.x] = b1[threadIdx.x];
        sW2[threadIdx.x] = W2[threadIdx.x];
    }
    if (threadIdx.x == 0) sb2 = b2[0];
    __syncthreads();

    const int i = blockIdx.x * blockDim.x + threadIdx.x;
    if (i >= batch) return;

    const int g  = gidx[i];
    const int it = iidx[i];
    const float ginv = 1.f / (float)gcnt[g];
    const float2* __restrict__ ge2 =
        (const float2*)(group_sums + (size_t)g * EMB_DIM);
    const float2* __restrict__ ie2 =
        (const float2*)(item_emb + (size_t)it * EMB_DIM);

    float h[8];
    #pragma unroll
    for (int k = 0; k < 8; ++k) h[k] = sb1[k];

    #pragma unroll 4
    for (int d2 = 0; d2 < 32; ++d2) {
        float2 e = ge2[d2];
        e.x *= ginv; e.y *= ginv;
        const int d0 = 2 * d2;
        #pragma unroll
        for (int k = 0; k < 8; ++k) {
            h[k] += e.x * sW1[(d0    ) * 8 + k];
            h[k] += e.y * sW1[(d0 + 1) * 8 + k];
        }
    }
    #pragma unroll 4
    for (int d2 = 0; d2 < 32; ++d2) {
        const float2 e = ie2[d2];
        const int d0 = 2 * d2 + EMB_DIM;
        #pragma unroll
        for (int k = 0; k < 8; ++k) {
            h[k] += e.x * sW1[(d0    ) * 8 + k];
            h[k] += e.y * sW1[(d0 + 1) * 8 + k];
        }
    }

    float y = sb2;
    #pragma unroll
    for (int k = 0; k < 8; ++k)
        y += fmaxf(h[k], 0.0f) * sW2[k];

    out[i] = 1.0f / (1.0f + expf(-y));
}

// ---------------------------------------------------------------------------
extern "C" void kernel_launch(void* const* d_in, const int* in_sizes, int n_in,
                              void* d_out, int out_size)
{
    const float* item_emb = (const float*)d_in[0];
    const float* ui       = (const float*)d_in[1];
    const float* gu       = (const float*)d_in[2];
    const float* W1       = (const float*)d_in[3];
    const float* b1       = (const float*)d_in[4];
    const float* W2       = (const float*)d_in[5];
    const float* b2       = (const float*)d_in[6];
    const int*   gidx     = (const int*)d_in[7];
    const int*   iidx     = (const int*)d_in[8];
    float* out            = (float*)d_out;

    float* user_sums;  int* ucnt;
    float* group_sums; int* gcnt;
    cudaGetSymbolAddress((void**)&user_sums,  g_user_sums);
    cudaGetSymbolAddress((void**)&ucnt,       g_ucnt);
    cudaGetSymbolAddress((void**)&group_sums, g_group_sums);
    cudaGetSymbolAddress((void**)&gcnt,       g_gcnt);

    // opt-in to >48KB dynamic smem (idempotent; not a stream op)
    cudaFuncSetAttribute(panel_aggregate<false>,
                         cudaFuncAttributeMaxDynamicSharedMemorySize, SMEM_BYTES);
    cudaFuncSetAttribute(panel_aggregate<true>,
                         cudaFuncAttributeMaxDynamicSharedMemorySize, SMEM_BYTES);

    // 0) zero accumulators
    zero_kernel<<<(NUM_USERS * EMB_DIM + 255) / 256, 256>>>();

    // 1) user_sums/ucnt: aggregate item_emb over ui hits (panelized)
    panel_aggregate<false>
        <<<dim3(NPANELS, ROWGRP), 512, SMEM_BYTES>>>(
            ui, item_emb, (const int*)nullptr, user_sums, ucnt, NUM_USERS);

    // 2) group_sums/gcnt: aggregate (user_sums / clamp(ucnt,1)) over gu hits
    panel_aggregate<true>
        <<<dim3(NPANELS, ROWGRP), 512, SMEM_BYTES>>>(
            gu, user_sums, ucnt, group_sums, gcnt, NUM_GROUPS);

    // 3) MLP head (divides group_sums by raw gcnt)
    {
        const int threads = 128;
        const int grid = (BATCH + threads - 1) / threads;
        mlp_kernel<<<grid, threads>>>(group_sums, gcnt, item_emb,
                                      W1, b1, W2, b2, gidx, iidx,
                                      out, BATCH);
    }
}

// round 12
// speedup vs baseline: 2.0233x; 2.0233x over previous
#include <cuda_runtime.h>
#include <math.h>
#include <stdint.h>

#define NUM_ITEMS  10000
#define NUM_USERS  10000
#define NUM_GROUPS 5000
#define EMB_DIM    64
#define BATCH      16384
#define NCOLS      10000

#define WCAP   512            // k1 per-warp hit-index buffer
#define BLKF4  128            // float4 per cp.async stream block (2 KB)
#define GCAP   320            // CSR capacity per gu row (mean ~100, 20+ sigma margin)

// Scratch (allocation-free rule: __device__ globals)
__device__ float    g_user_embeds[NUM_USERS * EMB_DIM];    // divided (clamped cnt)
__device__ float    g_group_embeds[NUM_GROUPS * EMB_DIM];  // divided (raw cnt)
__device__ uint16_t g_gcsr[NUM_GROUPS * GCAP];             // gu hit indices
__device__ int      g_gcnt[NUM_GROUPS];                    // gu hit counts

// ---- cp.async helpers -----------------------------------------------------
__device__ __forceinline__ void cp_async16(void* smem, const void* gmem) {
    unsigned saddr = (unsigned)__cvta_generic_to_shared(smem);
    asm volatile("cp.async.cg.shared.global [%0], [%1], 16;"
                 :: "r"(saddr), "l"(gmem));
}
#define CP_COMMIT()  asm volatile("cp.async.commit_group;" ::: "memory")
#define CP_WAIT(n)   asm volatile("cp.async.wait_group %0;" :: "n"(n) : "memory")

// ---- byte-pack detection: entries are exactly {0.0f,1.0f}; byte3==0x3F iff 1
__device__ __forceinline__ unsigned detect4(float4 v) {
    const unsigned p = __byte_perm(__float_as_uint(v.x), __float_as_uint(v.y), 0x0073) |
                       __byte_perm(__float_as_uint(v.z), __float_as_uint(v.w), 0x7300);
    return p & 0x01010101u;
}

// ---------------------------------------------------------------------------
// Batched gather from smem idx list (R8/R10 form): 8 indep LDG.64 in flight.
// ---------------------------------------------------------------------------
__device__ __forceinline__ void load_batch(const int* __restrict__ idxbuf, int j,
                                           int lane, const float2* __restrict__ emb2,
                                           float2* e)
{
    int id[8];
    #pragma unroll
    for (int t = 0; t < 8; ++t) id[t] = idxbuf[j + t];
    #pragma unroll
    for (int t = 0; t < 8; ++t) e[t] = emb2[id[t] * 32 + lane];
}

__device__ __forceinline__ void gather_accumulate(const int* __restrict__ idxbuf,
                                                  int nh, int lane,
                                                  const float2* __restrict__ emb2,
                                                  float2& acc)
{
    const int nfull = nh & ~7;
    if (nfull) {
        float2 ea[8];
        load_batch(idxbuf, 0, lane, emb2, ea);
        for (int j = 8; j < nfull; j += 8) {
            float2 eb[8];
            load_batch(idxbuf, j, lane, emb2, eb);
            #pragma unroll
            for (int t = 0; t < 8; ++t) { acc.x += ea[t].x; acc.y += ea[t].y; }
            #pragma unroll
            for (int t = 0; t < 8; ++t) ea[t] = eb[t];
        }
        #pragma unroll
        for (int t = 0; t < 8; ++t) { acc.x += ea[t].x; acc.y += ea[t].y; }
    }
    for (int j = nfull; j < nh; ++j) {
        const float2 e = emb2[idxbuf[j] * 32 + lane];
        acc.x += e.x; acc.y += e.y;
    }
}

// ---------------------------------------------------------------------------
// FUSED kernel: 3750 blocks, round-robin roles so both populations co-reside.
//   role k1  (2 of 3): R10 pipeline — ui row scan via cp.async stage + smem
//                      idx buffer + deferred batched gather of item_emb.
//   role scan(1 of 3): gu row pure stream (reg-prefetch MLP=8, __ldcs) ->
//                      uint16 CSR hit list + count (no gather: soaks the DRAM
//                      headroom k1's mixed pattern leaves idle).
// ---------------------------------------------------------------------------
__global__ __launch_bounds__(128)
void fused_kernel(const float* __restrict__ ui,
                  const float* __restrict__ gu,
                  const float* __restrict__ item_emb)
{
    __shared__ float4 s_stage[4][2][BLKF4];       // 16 KB (k1 role)
    __shared__ int    s_idx[4][WCAP];             // 8 KB  (k1 role)
    __shared__ int    s_nh[4];

    const int lane = threadIdx.x & 31;
    const int wl   = threadIdx.x >> 5;
    const int b    = blockIdx.x;
    const int r    = b % 3;
    const int q    = b / 3;                       // 0..1249

    if (lane == 0) s_nh[wl] = 0;
    __syncwarp();

    if (r == 2) {
        // ================= scan role: gu row -> CSR =================
        const int row = q * 4 + wl;               // 0..4999
        const float4* __restrict__ row4 = (const float4*)(gu + (size_t)row * NCOLS);
        const int ncols4 = NCOLS / 4;             // 2500
        uint16_t* __restrict__ csr = g_gcsr + (size_t)row * GCAP;

        for (int base = 0; base < ncols4; base += 256) {
            float4 v[8];
            #pragma unroll
            for (int u = 0; u < 8; ++u) {
                const int jj = base + u * 32 + lane;
                v[u] = (jj < ncols4) ? __ldcs(&row4[jj])
                                     : make_float4(0.f, 0.f, 0.f, 0.f);
            }
            unsigned br[8];
            unsigned ucnt = 0u;
            #pragma unroll
            for (int u = 0; u < 8; ++u) {
                br[u] = detect4(v[u]);
                ucnt = __dp4a(br[u], 0x01010101u, ucnt);
            }
            int off = atomicAdd(&s_nh[wl], (int)ucnt);
            const int ebase = base * 4 + lane * 4;
            #pragma unroll
            for (int u = 0; u < 8; ++u) {
                unsigned bm = br[u];
                while (bm) {
                    const int k = __ffs(bm) - 1;
                    bm &= bm - 1;
                    if (off < GCAP)
                        csr[off] = (uint16_t)(ebase + u * 128 + (k >> 3));
                    ++off;
                }
            }
        }
        __syncwarp();
        if (lane == 0) g_gcnt[row] = s_nh[wl];
        return;
    }

    // ================= k1 role: ui row -> user_embeds (R10 pipeline) =========
    const int row = (q * 2 + r) * 4 + wl;         // 0..9999
    const int ncols4 = NCOLS / 4;
    const int nblk   = (ncols4 + BLKF4 - 1) / BLKF4;
    const float4* __restrict__ row4 = (const float4*)(ui + (size_t)row * NCOLS);
    const float2* __restrict__ emb2 = (const float2*)item_emb;
    int* idxbuf = s_idx[wl];

    float2 acc = make_float2(0.f, 0.f);
    int nh = 0, tot = 0;

    {   // prologue: stage block 0
        #pragma unroll
        for (int u = 0; u < 4; ++u) {
            const int jj = u * 32 + lane;
            if (jj < ncols4) cp_async16(&s_stage[wl][0][u * 32 + lane], &row4[jj]);
        }
        CP_COMMIT();
    }

    for (int bb = 0; bb < nblk; ++bb) {
        if (bb + 1 < nblk) {
            const int nb = (bb + 1) * BLKF4;
            #pragma unroll
            for (int u = 0; u < 4; ++u) {
                const int jj = nb + u * 32 + lane;
                if (jj < ncols4)
                    cp_async16(&s_stage[wl][(bb + 1) & 1][u * 32 + lane], &row4[jj]);
            }
        }
        CP_COMMIT();
        CP_WAIT(1);

        const int base = bb * BLKF4;
        const float4* stage = s_stage[wl][bb & 1];
        unsigned br[4];
        unsigned ucnt = 0u;
        #pragma unroll
        for (int u = 0; u < 4; ++u) {
            const int jj = base + u * 32 + lane;
            float4 v = (jj < ncols4) ? stage[u * 32 + lane]
                                     : make_float4(0.f, 0.f, 0.f, 0.f);
            br[u] = detect4(v);
            ucnt = __dp4a(br[u], 0x01010101u, ucnt);
        }
        const int cnt  = (int)ucnt;
        const int btot = __reduce_add_sync(0xffffffffu, cnt);
        if (nh + btot > WCAP) {
            __syncwarp();
            gather_accumulate(idxbuf, nh, lane, emb2, acc);
            tot += nh; nh = 0;
            if (lane == 0) s_nh[wl] = 0;
            __syncwarp();
        }
        int off = atomicAdd(&s_nh[wl], cnt);
        const int ebase = base * 4 + lane * 4;
        #pragma unroll
        for (int u = 0; u < 4; ++u) {
            unsigned bm = br[u];
            while (bm) {
                const int k = __ffs(bm) - 1;
                bm &= bm - 1;
                idxbuf[off++] = ebase + u * 128 + (k >> 3);
            }
        }
        nh += btot;
        __syncwarp();
    }
    CP_WAIT(0);

    gather_accumulate(idxbuf, nh, lane, emb2, acc);
    tot += nh;

    const float inv = 1.0f / fmaxf((float)tot, 1.0f);   // clamped divisor (k1)
    float2* __restrict__ out2 = (float2*)(g_user_embeds + (size_t)row * EMB_DIM);
    out2[lane] = make_float2(acc.x * inv, acc.y * inv);
}

// ---------------------------------------------------------------------------
// Group gather: one warp per group; batched gather of user_embeds rows from
// the CSR list (L2-resident source). Raw-count divisor (guaranteed >= 1).
// Correct slow path if a CSR row ever overflowed (statistically never).
// ---------------------------------------------------------------------------
__global__ __launch_bounds__(128)
void group_gather_kernel(const float* __restrict__ gu)
{
    const int lane = threadIdx.x & 31;
    const int wl   = threadIdx.x >> 5;
    const int row  = blockIdx.x * 4 + wl;
    if (row >= NUM_GROUPS) return;

    const float2* __restrict__ ue2 = (const float2*)g_user_embeds;
    const int cnt = g_gcnt[row];
    float2 acc = make_float2(0.f, 0.f);

    if (cnt <= GCAP) {
        const uint16_t* __restrict__ csr = g_gcsr + (size_t)row * GCAP;
        const int nfull = cnt & ~7;
        if (nfull) {
            float2 ea[8];
            int id[8];
            #pragma unroll
            for (int t = 0; t < 8; ++t) id[t] = csr[t];
            #pragma unroll
            for (int t = 0; t < 8; ++t) ea[t] = ue2[id[t] * 32 + lane];
            for (int j = 8; j < nfull; j += 8) {
                float2 eb[8];
                #pragma unroll
                for (int t = 0; t < 8; ++t) id[t] = csr[j + t];
                #pragma unroll
                for (int t = 0; t < 8; ++t) eb[t] = ue2[id[t] * 32 + lane];
                #pragma unroll
                for (int t = 0; t < 8; ++t) { acc.x += ea[t].x; acc.y += ea[t].y; }
                #pragma unroll
                for (int t = 0; t < 8; ++t) ea[t] = eb[t];
            }
            #pragma unroll
            for (int t = 0; t < 8; ++t) { acc.x += ea[t].x; acc.y += ea[t].y; }
        }
        for (int j = nfull; j < cnt; ++j) {
            const float2 e = ue2[(int)csr[j] * 32 + lane];
            acc.x += e.x; acc.y += e.y;
        }
    } else {
        // slow path: rescan the gu row inline (never expected)
        const float4* __restrict__ row4 = (const float4*)(gu + (size_t)row * NCOLS);
        for (int base = 0; base < NCOLS / 4; base += 32) {
            const int j4 = base + lane;
            float4 v = (j4 < NCOLS / 4) ? row4[j4] : make_float4(0.f, 0.f, 0.f, 0.f);
            #pragma unroll
            for (int c = 0; c < 4; ++c) {
                unsigned m = __ballot_sync(0xffffffffu, (&v.x)[c] > 0.f);
                while (m) {
                    const int l = __ffs(m) - 1;
                    m &= m - 1;
                    const float2 e = ue2[((base + l) * 4 + c) * 32 + lane];
                    acc.x += e.x; acc.y += e.y;
                }
            }
        }
    }

    const float inv = 1.0f / (float)cnt;          // raw divisor, no clamp
    float2* __restrict__ out2 = (float2*)(g_group_embeds + (size_t)row * EMB_DIM);
    out2[lane] = make_float2(acc.x * inv, acc.y * inv);
}

// ---------------------------------------------------------------------------
// MLP, 4 threads per batch element (32 concat-dims each), shfl-reduced.
// ---------------------------------------------------------------------------
__global__ __launch_bounds__(256)
void mlp_kernel(const float* __restrict__ item_emb,
                const float* __restrict__ W1,  // [128, 8]
                const float* __restrict__ b1,  // [8]
                const float* __restrict__ W2,  // [8, 1]
                const float* __restrict__ b2,  // [1]
                const int*   __restrict__ gidx,
                const int*   __restrict__ iidx,
                float* __restrict__ out)
{
    __shared__ float sW1[2 * EMB_DIM * 8];
    __shared__ float sb1[8];
    __shared__ float sW2[8];
    __shared__ float sb2;

    for (int i = threadIdx.x; i < 2 * EMB_DIM * 8; i += blockDim.x)
        sW1[i] = W1[i];
    if (threadIdx.x < 8) {
        sb1[threadIdx.x] = b1[threadIdx.x];
        sW2[threadIdx.x] = W2[threadIdx.x];
    }
    if (threadIdx.x == 0) sb2 = b2[0];
    __syncthreads();

    const int gtid = blockIdx.x * 256 + threadIdx.x;
    const int elem = gtid >> 2;
    const int qq   = gtid & 3;                    // which 32-dim slice
    if (elem >= BATCH) return;

    const int d0 = qq * 32;                       // concat dims [d0, d0+32)
    const float* src = (qq < 2)
        ? (g_group_embeds + (size_t)gidx[elem] * EMB_DIM + d0)
        : (item_emb       + (size_t)iidx[elem] * EMB_DIM + (d0 - EMB_DIM));

    float h[8];
    #pragma unroll
    for (int k = 0; k < 8; ++k) h[k] = (qq == 0) ? sb1[k] : 0.f;

    const float4* __restrict__ s4 = (const float4*)src;
    #pragma unroll
    for (int j = 0; j < 8; ++j) {                 // 8 x float4 = 32 dims
        const float4 e = s4[j];
        const int dd = d0 + 4 * j;
        #pragma unroll
        for (int k = 0; k < 8; ++k) {
            h[k] += e.x * sW1[(dd    ) * 8 + k];
            h[k] += e.y * sW1[(dd + 1) * 8 + k];
            h[k] += e.z * sW1[(dd + 2) * 8 + k];
            h[k] += e.w * sW1[(dd + 3) * 8 + k];
        }
    }

    // reduce h across the element's 4 threads (lanes differ in bits 0,1)
    #pragma unroll
    for (int k = 0; k < 8; ++k) {
        h[k] += __shfl_xor_sync(0xffffffffu, h[k], 1);
        h[k] += __shfl_xor_sync(0xffffffffu, h[k], 2);
    }

    if (qq == 0) {
        float y = sb2;
        #pragma unroll
        for (int k = 0; k < 8; ++k)
            y += fmaxf(h[k], 0.0f) * sW2[k];
        out[elem] = 1.0f / (1.0f + expf(-y));
    }
}

// ---------------------------------------------------------------------------
extern "C" void kernel_launch(void* const* d_in, const int* in_sizes, int n_in,
                              void* d_out, int out_size)
{
    const float* item_emb = (const float*)d_in[0];
    const float* ui       = (const float*)d_in[1];
    const float* gu       = (const float*)d_in[2];
    const float* W1       = (const float*)d_in[3];
    const float* b1       = (const float*)d_in[4];
    const float* W2       = (const float*)d_in[5];
    const float* b2       = (const float*)d_in[6];
    const int*   gidx     = (const int*)d_in[7];
    const int*   iidx     = (const int*)d_in[8];
    float* out            = (float*)d_out;

    // 1) fused: k1 (ui scan+gather -> user_embeds) || gu scan -> CSR
    fused_kernel<<<3750, 128>>>(ui, gu, item_emb);

    // 2) group gather from CSR (user_embeds L2-resident)
    group_gather_kernel<<<1250, 128>>>(gu);

    // 3) MLP head (x4 thread parallelism)
    mlp_kernel<<<(BATCH * 4) / 256, 256>>>(item_emb, W1, b1, W2, b2,
                                           gidx, iidx, out);
}